// round 2
// baseline (speedup 1.0000x reference)
#include <cuda_runtime.h>
#include <math.h>

// Problem constants
#define BATCH 4
#define NH 16
#define DM 1024
#define LQ 2048
#define LK 2048
#define DHEAD 64
#define ATT_SCALE 0.125f   // 1/sqrt(64)

// Scratch for projected q/k/v: [B, S, H, D] fp32 (32 MB each)
__device__ float g_q[BATCH * LQ * NH * DHEAD];
__device__ float g_k[BATCH * LK * NH * DHEAD];
__device__ float g_v[BATCH * LK * NH * DHEAD];

// ---------------------------------------------------------------------------
// Projection GEMM: C[M,N] = A[M,K] @ W[K,N] + bias[N]
// M = 8192, N = 1024, K = 1024. 128x128 tile, BK=16, 8x8 per thread,
// double-buffered smem.
// ---------------------------------------------------------------------------
#define GBM 128
#define GBN 128
#define GBK 16
#define GM 8192
#define GN 1024
#define GK 1024

template <int WHICH>
__global__ __launch_bounds__(256) void proj_gemm(const float* __restrict__ A,
                                                 const float* __restrict__ W,
                                                 const float* __restrict__ bias) {
    float* C = (WHICH == 0) ? g_q : (WHICH == 1) ? g_k : g_v;

    __shared__ __align__(16) float As[2][GBK][GBM + 4];  // transposed: [k][m]
    __shared__ __align__(16) float Bs[2][GBK][GBN + 4];  // natural:    [k][n]

    const int tid = threadIdx.x;
    const int tx = tid & 15;
    const int ty = tid >> 4;
    const int rowBase = blockIdx.y * GBM;
    const int colBase = blockIdx.x * GBN;

    float acc[8][8];
#pragma unroll
    for (int i = 0; i < 8; i++)
#pragma unroll
        for (int j = 0; j < 8; j++) acc[i][j] = 0.f;

    float4 ra[2], rb[2];

    // Prologue: load tile 0 (gmem -> regs -> smem buf 0)
#pragma unroll
    for (int i = 0; i < 2; i++) {
        int lin = tid + i * 256;
        int ar = lin >> 2, kc = (lin & 3) << 2;
        ra[i] = *(const float4*)&A[(size_t)(rowBase + ar) * GK + kc];
        int br = lin >> 5, bc = (lin & 31) << 2;
        rb[i] = *(const float4*)&W[(size_t)br * GN + colBase + bc];
    }
#pragma unroll
    for (int i = 0; i < 2; i++) {
        int lin = tid + i * 256;
        int ar = lin >> 2, kc = (lin & 3) << 2;
        As[0][kc + 0][ar] = ra[i].x;
        As[0][kc + 1][ar] = ra[i].y;
        As[0][kc + 2][ar] = ra[i].z;
        As[0][kc + 3][ar] = ra[i].w;
        int br = lin >> 5, bc = (lin & 31) << 2;
        *(float4*)&Bs[0][br][bc] = rb[i];
    }
    __syncthreads();

    int buf = 0;
    const int NT = GK / GBK;  // 64
    for (int t = 0; t < NT; t++) {
        // Prefetch next tile into registers (overlaps with compute below)
        if (t + 1 < NT) {
            int kb = (t + 1) * GBK;
#pragma unroll
            for (int i = 0; i < 2; i++) {
                int lin = tid + i * 256;
                int ar = lin >> 2, kc = (lin & 3) << 2;
                ra[i] = *(const float4*)&A[(size_t)(rowBase + ar) * GK + kb + kc];
                int br = lin >> 5, bc = (lin & 31) << 2;
                rb[i] = *(const float4*)&W[(size_t)(kb + br) * GN + colBase + bc];
            }
        }
#pragma unroll
        for (int k = 0; k < GBK; k++) {
            float4 a0 = *(const float4*)&As[buf][k][ty * 8];
            float4 a1 = *(const float4*)&As[buf][k][ty * 8 + 4];
            float4 b0 = *(const float4*)&Bs[buf][k][tx * 8];
            float4 b1 = *(const float4*)&Bs[buf][k][tx * 8 + 4];
            float av[8] = {a0.x, a0.y, a0.z, a0.w, a1.x, a1.y, a1.z, a1.w};
            float bv[8] = {b0.x, b0.y, b0.z, b0.w, b1.x, b1.y, b1.z, b1.w};
#pragma unroll
            for (int i = 0; i < 8; i++)
#pragma unroll
                for (int j = 0; j < 8; j++) acc[i][j] += av[i] * bv[j];
        }
        if (t + 1 < NT) {
            int nbuf = buf ^ 1;
#pragma unroll
            for (int i = 0; i < 2; i++) {
                int lin = tid + i * 256;
                int ar = lin >> 2, kc = (lin & 3) << 2;
                As[nbuf][kc + 0][ar] = ra[i].x;
                As[nbuf][kc + 1][ar] = ra[i].y;
                As[nbuf][kc + 2][ar] = ra[i].z;
                As[nbuf][kc + 3][ar] = ra[i].w;
                int br = lin >> 5, bc = (lin & 31) << 2;
                *(float4*)&Bs[nbuf][br][bc] = rb[i];
            }
            __syncthreads();
            buf = nbuf;
        }
    }

    // Epilogue: add bias, write C
    float4 bia0 = *(const float4*)&bias[colBase + tx * 8];
    float4 bia1 = *(const float4*)&bias[colBase + tx * 8 + 4];
    float bb[8] = {bia0.x, bia0.y, bia0.z, bia0.w, bia1.x, bia1.y, bia1.z, bia1.w};
#pragma unroll
    for (int i = 0; i < 8; i++) {
        size_t row = (size_t)(rowBase + ty * 8 + i);
        float4 o0 = make_float4(acc[i][0] + bb[0], acc[i][1] + bb[1],
                                acc[i][2] + bb[2], acc[i][3] + bb[3]);
        float4 o1 = make_float4(acc[i][4] + bb[4], acc[i][5] + bb[5],
                                acc[i][6] + bb[6], acc[i][7] + bb[7]);
        *(float4*)&C[row * GN + colBase + tx * 8] = o0;
        *(float4*)&C[row * GN + colBase + tx * 8 + 4] = o1;
    }
}

// ---------------------------------------------------------------------------
// Flash-style attention, fp32.
// Block: one (b, h, 128-query tile). 256 threads as 16(tq) x 16(tk).
// Thread owns 8 query rows (tq) and 4 key-cols / 4 d-cols (tk).
// Smem pitches chosen from bank math: QP=64 (broadcast reads, float4 stores),
// KP=65 (2-way scalar), VP=68 (float4 both ways), PP=66 (2-way stores).
// ---------------------------------------------------------------------------
#define AQ 128
#define AK 64
#define QP 64
#define KP 65
#define VP 68
#define PP 66
#define ASMEM_FLOATS (AQ * QP + AK * KP + AK * VP + AQ * PP)   // 25152
#define ASMEM_BYTES (ASMEM_FLOATS * 4 + LK * 4)                // 108800

__global__ __launch_bounds__(256, 2) void attn_kernel(const int* __restrict__ mask,
                                                      float* __restrict__ out) {
    extern __shared__ __align__(16) float sm[];
    float* Qs = sm;                      // [AQ][QP]
    float* Ks = Qs + AQ * QP;            // [AK][KP]
    float* Vs = Ks + AK * KP;            // [AK][VP]
    float* Ps = Vs + AK * VP;            // [AQ][PP]
    int* Ms = (int*)(Ps + AQ * PP);      // [LK]

    const int tid = threadIdx.x;
    const int tk = tid & 15;
    const int tq = tid >> 4;
    const int qb = blockIdx.x;
    const int h = blockIdx.y;
    const int b = blockIdx.z;
    const int q0 = qb * AQ;

    const float* gq = g_q + (size_t)b * LQ * (NH * DHEAD) + h * DHEAD;
    const float* gk = g_k + (size_t)b * LK * (NH * DHEAD) + h * DHEAD;
    const float* gv = g_v + (size_t)b * LK * (NH * DHEAD) + h * DHEAD;

    // Mask row for this batch -> smem (reused by all 32 key tiles)
    for (int i = tid; i < LK; i += 256) Ms[i] = mask[b * LK + i];

    // Q tile [128 x 64] -> smem (natural layout, float4)
#pragma unroll
    for (int i = 0; i < 8; i++) {
        int lin = tid + i * 256;
        int r = lin >> 4, c = (lin & 15) << 2;
        float4 v = *(const float4*)&gq[(size_t)(q0 + r) * (NH * DHEAD) + c];
        *(float4*)&Qs[r * QP + c] = v;
    }
    __syncthreads();

    float m_i[8], l_i[8], O[8][4];
#pragma unroll
    for (int i = 0; i < 8; i++) {
        m_i[i] = -INFINITY;
        l_i[i] = 0.f;
        O[i][0] = O[i][1] = O[i][2] = O[i][3] = 0.f;
    }

    const float* qbase = Qs + (tq * 8) * QP;
    const float* pbase = Ps + (tq * 8) * PP;

    for (int kt = 0; kt < LK; kt += AK) {
        // Load K,V tiles [64 x 64]
#pragma unroll
        for (int i = 0; i < 4; i++) {
            int lin = tid + i * 256;
            int r = lin >> 4, c = (lin & 15) << 2;
            float4 kv = *(const float4*)&gk[(size_t)(kt + r) * (NH * DHEAD) + c];
            Ks[r * KP + c + 0] = kv.x;
            Ks[r * KP + c + 1] = kv.y;
            Ks[r * KP + c + 2] = kv.z;
            Ks[r * KP + c + 3] = kv.w;
            float4 vv = *(const float4*)&gv[(size_t)(kt + r) * (NH * DHEAD) + c];
            *(float4*)&Vs[r * VP + c] = vv;
        }
        __syncthreads();

        // S = Q . K^T  (8x4 per thread, reduction over d)
        float S[8][4];
#pragma unroll
        for (int ii = 0; ii < 8; ii++)
            S[ii][0] = S[ii][1] = S[ii][2] = S[ii][3] = 0.f;

        const float* k0p = Ks + (tk * 4 + 0) * KP;
        const float* k1p = Ks + (tk * 4 + 1) * KP;
        const float* k2p = Ks + (tk * 4 + 2) * KP;
        const float* k3p = Ks + (tk * 4 + 3) * KP;
#pragma unroll 4
        for (int d = 0; d < DHEAD; d++) {
            float a_[8];
#pragma unroll
            for (int ii = 0; ii < 8; ii++) a_[ii] = qbase[ii * QP + d];
            float b0 = k0p[d], b1 = k1p[d], b2 = k2p[d], b3 = k3p[d];
#pragma unroll
            for (int ii = 0; ii < 8; ii++) {
                S[ii][0] += a_[ii] * b0;
                S[ii][1] += a_[ii] * b1;
                S[ii][2] += a_[ii] * b2;
                S[ii][3] += a_[ii] * b3;
            }
        }

        // Scale + key-padding mask (matches reference: masked -> -1e9 exactly)
        int mk0 = Ms[kt + tk * 4 + 0];
        int mk1 = Ms[kt + tk * 4 + 1];
        int mk2 = Ms[kt + tk * 4 + 2];
        int mk3 = Ms[kt + tk * 4 + 3];
#pragma unroll
        for (int ii = 0; ii < 8; ii++) {
            S[ii][0] = (mk0 == 0) ? -1e9f : S[ii][0] * ATT_SCALE;
            S[ii][1] = (mk1 == 0) ? -1e9f : S[ii][1] * ATT_SCALE;
            S[ii][2] = (mk2 == 0) ? -1e9f : S[ii][2] * ATT_SCALE;
            S[ii][3] = (mk3 == 0) ? -1e9f : S[ii][3] * ATT_SCALE;
        }

        // Online softmax update per query row (16-lane tk-group reductions)
#pragma unroll
        for (int ii = 0; ii < 8; ii++) {
            float mx = fmaxf(fmaxf(S[ii][0], S[ii][1]), fmaxf(S[ii][2], S[ii][3]));
            mx = fmaxf(mx, __shfl_xor_sync(0xffffffffu, mx, 1));
            mx = fmaxf(mx, __shfl_xor_sync(0xffffffffu, mx, 2));
            mx = fmaxf(mx, __shfl_xor_sync(0xffffffffu, mx, 4));
            mx = fmaxf(mx, __shfl_xor_sync(0xffffffffu, mx, 8));
            float mnew = fmaxf(m_i[ii], mx);
            float sc = __expf(m_i[ii] - mnew);
            m_i[ii] = mnew;
            float ls = 0.f;
#pragma unroll
            for (int jj = 0; jj < 4; jj++) {
                float p = __expf(S[ii][jj] - mnew);
                S[ii][jj] = p;
                ls += p;
            }
            ls += __shfl_xor_sync(0xffffffffu, ls, 1);
            ls += __shfl_xor_sync(0xffffffffu, ls, 2);
            ls += __shfl_xor_sync(0xffffffffu, ls, 4);
            ls += __shfl_xor_sync(0xffffffffu, ls, 8);
            l_i[ii] = l_i[ii] * sc + ls;
            O[ii][0] *= sc;
            O[ii][1] *= sc;
            O[ii][2] *= sc;
            O[ii][3] *= sc;
        }

        // P tile -> smem
#pragma unroll
        for (int ii = 0; ii < 8; ii++) {
#pragma unroll
            for (int jj = 0; jj < 4; jj++)
                Ps[(tq * 8 + ii) * PP + tk * 4 + jj] = S[ii][jj];
        }
        __syncthreads();

        // O += P . V  (reduction over kj)
#pragma unroll 4
        for (int kj = 0; kj < AK; kj++) {
            float4 v4 = *(const float4*)&Vs[kj * VP + tk * 4];
#pragma unroll
            for (int ii = 0; ii < 8; ii++) {
                float p = pbase[ii * PP + kj];
                O[ii][0] += p * v4.x;
                O[ii][1] += p * v4.y;
                O[ii][2] += p * v4.z;
                O[ii][3] += p * v4.w;
            }
        }
        __syncthreads();  // protect Ks/Vs/Ps before next iteration's loads
    }

    // Normalize and write out: [B, LQ, H*DV]
#pragma unroll
    for (int ii = 0; ii < 8; ii++) {
        float inv = 1.f / l_i[ii];
        size_t row = (size_t)b * LQ + q0 + tq * 8 + ii;
        float4 o = make_float4(O[ii][0] * inv, O[ii][1] * inv,
                               O[ii][2] * inv, O[ii][3] * inv);
        *(float4*)&out[row * (NH * DHEAD) + h * DHEAD + tk * 4] = o;
    }
}

// ---------------------------------------------------------------------------
extern "C" void kernel_launch(void* const* d_in, const int* in_sizes, int n_in,
                              void* d_out, int out_size) {
    (void)in_sizes;
    (void)n_in;
    (void)out_size;
    const float* Q = (const float*)d_in[0];
    const float* K = (const float*)d_in[1];
    const float* V = (const float*)d_in[2];
    const int* mask = (const int*)d_in[3];
    const float* Wq = (const float*)d_in[4];
    const float* bq = (const float*)d_in[5];
    const float* Wk = (const float*)d_in[6];
    const float* bk = (const float*)d_in[7];
    const float* Wv = (const float*)d_in[8];
    const float* bv = (const float*)d_in[9];
    float* out = (float*)d_out;

    // Immediate (non-stream) API; called every invocation, capture-safe.
    cudaFuncSetAttribute(attn_kernel, cudaFuncAttributeMaxDynamicSharedMemorySize,
                         ASMEM_BYTES);

    dim3 gg(GN / GBN, GM / GBM);  // (8, 64)
    proj_gemm<0><<<gg, 256>>>(Q, Wq, bq);
    proj_gemm<1><<<gg, 256>>>(K, Wk, bk);
    proj_gemm<2><<<gg, 256>>>(V, Wv, bv);

    dim3 ag(LQ / AQ, NH, BATCH);  // (16, 16, 4)
    attn_kernel<<<ag, 256, ASMEM_BYTES>>>(mask, out);
}

// round 6
// speedup vs baseline: 1.2940x; 1.2940x over previous
#include <cuda_runtime.h>
#include <cuda_bf16.h>
#include <cstdint>
#include <math.h>

// ---------------------------------------------------------------------------
// Problem constants
// ---------------------------------------------------------------------------
#define BATCH 4
#define NH 16
#define DM 1024
#define LQ 2048
#define LK 2048
#define DHEAD 64
#define ATT_SCALE 0.125f   // 1/sqrt(64)

#define GM 8192            // B*LQ
#define GN 1024            // H*DHEAD
#define GK 1024            // D_MODEL

// Scratch
__device__ float g_q[BATCH * LQ * NH * DHEAD];
__device__ float g_k[BATCH * LK * NH * DHEAD];
__device__ float g_v[BATCH * LK * NH * DHEAD];
__device__ __nv_bfloat16 g_ahi[GM * GK];
__device__ __nv_bfloat16 g_alo[GM * GK];
__device__ __nv_bfloat16 g_whi[GN * GK];   // transposed: [n][k]
__device__ __nv_bfloat16 g_wlo[GN * GK];

// ---------------------------------------------------------------------------
// Helpers (baseline-PTX only: ldmatrix / mma.sync / cp.async — no tcgen05)
// ---------------------------------------------------------------------------
__device__ __forceinline__ uint32_t smem_u32(const void* p) {
    uint32_t a;
    asm("{ .reg .u64 t; cvta.to.shared.u64 t, %1; cvt.u32.u64 %0, t; }"
        : "=r"(a) : "l"(p));
    return a;
}

__device__ __forceinline__ void cp_async16(uint32_t s, const void* g) {
    asm volatile("cp.async.cg.shared.global [%0], [%1], 16;" :: "r"(s), "l"(g));
}
#define CP_COMMIT() asm volatile("cp.async.commit_group;")
#define CP_WAIT(n) asm volatile("cp.async.wait_group %0;" :: "n"(n))

__device__ __forceinline__ void ldsm_x4(uint32_t* r, uint32_t addr) {
    asm volatile("ldmatrix.sync.aligned.m8n8.x4.shared.b16 {%0,%1,%2,%3}, [%4];"
                 : "=r"(r[0]), "=r"(r[1]), "=r"(r[2]), "=r"(r[3]) : "r"(addr));
}
__device__ __forceinline__ void ldsm_x2(uint32_t* r, uint32_t addr) {
    asm volatile("ldmatrix.sync.aligned.m8n8.x2.shared.b16 {%0,%1}, [%2];"
                 : "=r"(r[0]), "=r"(r[1]) : "r"(addr));
}

// D += A * B, m16n8k16, bf16 inputs, fp32 accumulate
__device__ __forceinline__ void mma16816(float* c, const uint32_t* a, const uint32_t* b) {
    asm volatile(
        "mma.sync.aligned.m16n8k16.row.col.f32.bf16.bf16.f32 "
        "{%0,%1,%2,%3}, {%4,%5,%6,%7}, {%8,%9}, {%0,%1,%2,%3};"
        : "+f"(c[0]), "+f"(c[1]), "+f"(c[2]), "+f"(c[3])
        : "r"(a[0]), "r"(a[1]), "r"(a[2]), "r"(a[3]), "r"(b[0]), "r"(b[1]));
}

// ---------------------------------------------------------------------------
// Conversion: fp32 -> (hi, lo) bf16 split
// ---------------------------------------------------------------------------
__device__ __forceinline__ uint32_t pack2(float a, float b) {
    __nv_bfloat162 t = __floats2bfloat162_rn(a, b);
    return *(uint32_t*)&t;
}

__global__ __launch_bounds__(256) void split_kernel(const float* __restrict__ x,
                                                    uint2* __restrict__ hi,
                                                    uint2* __restrict__ lo, int n4) {
    int i = blockIdx.x * 256 + threadIdx.x;
    if (i >= n4) return;
    float4 v = ((const float4*)x)[i];
    float h0 = __bfloat162float(__float2bfloat16(v.x));
    float h1 = __bfloat162float(__float2bfloat16(v.y));
    float h2 = __bfloat162float(__float2bfloat16(v.z));
    float h3 = __bfloat162float(__float2bfloat16(v.w));
    uint2 H, L;
    H.x = pack2(h0, h1);
    H.y = pack2(h2, h3);
    L.x = pack2(v.x - h0, v.y - h1);
    L.y = pack2(v.z - h2, v.w - h3);
    hi[i] = H;
    lo[i] = L;
}

// W [k][n] fp32 -> Wt hi/lo bf16 [n][k]
__global__ __launch_bounds__(256) void wtrans_kernel(const float* __restrict__ W,
                                                     __nv_bfloat16* __restrict__ thi,
                                                     __nv_bfloat16* __restrict__ tlo) {
    __shared__ float t[32][33];
    int n0 = blockIdx.x * 32, k0 = blockIdx.y * 32;
    int tx = threadIdx.x & 31, ty0 = threadIdx.x >> 5;  // 32 x 8
#pragma unroll
    for (int i = 0; i < 4; i++) {
        int ty = ty0 + i * 8;
        t[ty][tx] = W[(size_t)(k0 + ty) * GN + n0 + tx];
    }
    __syncthreads();
#pragma unroll
    for (int i = 0; i < 4; i++) {
        int ty = ty0 + i * 8;
        float v = t[tx][ty];  // = W[k0+tx][n0+ty]
        __nv_bfloat16 h = __float2bfloat16(v);
        size_t o = (size_t)(n0 + ty) * GK + k0 + tx;
        thi[o] = h;
        tlo[o] = __float2bfloat16(v - __bfloat162float(h));
    }
}

// ---------------------------------------------------------------------------
// Projection GEMM on mma.sync tensor cores:
// C[M,N] = A[M,K] @ Wt[N,K]^T + bias.  bf16 hi/lo split (hh + hl + lh).
// CTA tile 128x128, BK=32, cp.async double-buffered smem, 8 warps (2m x 4n),
// warp tile 64x32.
// ---------------------------------------------------------------------------
#define PBM 128
#define PBN 128
#define PBK 32
#define PPITCH 40                              // bf16 elements per smem row (80 B)
#define PTILE_B (128 * PPITCH * 2)             // 10240 B per tile
#define POFF_AHI 0
#define POFF_ALO (POFF_AHI + PTILE_B)
#define POFF_BHI (POFF_ALO + PTILE_B)
#define POFF_BLO (POFF_BHI + PTILE_B)
#define PSTAGE_B (4 * PTILE_B)                 // 40960 B
#define PSMEM_B (2 * PSTAGE_B)                 // 81920 B
#define PNCHUNK (GK / PBK)                     // 32

__global__ __launch_bounds__(256) void proj_mma(const __nv_bfloat16* __restrict__ Ahi,
                                                const __nv_bfloat16* __restrict__ Alo,
                                                const __nv_bfloat16* __restrict__ Bhi,
                                                const __nv_bfloat16* __restrict__ Blo,
                                                const float* __restrict__ bias,
                                                float* __restrict__ C) {
    extern __shared__ char smem[];
    const uint32_t sb = smem_u32(smem);
    const int tid = threadIdx.x;
    const int lane = tid & 31;
    const int warp = tid >> 5;
    const int wm = warp & 1;       // 0..1 -> m offset wm*64
    const int wn = warp >> 1;      // 0..3 -> n offset wn*32
    const int rowBase = blockIdx.y * PBM;
    const int colBase = blockIdx.x * PBN;

    float acc[4][4][4];
#pragma unroll
    for (int i = 0; i < 4; i++)
#pragma unroll
        for (int j = 0; j < 4; j++)
#pragma unroll
            for (int r = 0; r < 4; r++) acc[i][j][r] = 0.f;

    // ---- async tile loader: 512 x 16B per tile pair set ----
    auto load_chunk = [&](int stage, int kb) {
        uint32_t s0 = sb + stage * PSTAGE_B;
#pragma unroll
        for (int i = 0; i < 2; i++) {
            int c = tid + i * 256;         // 0..511
            int r = c >> 2;                // 0..127
            int col = (c & 3) * 8;         // 0,8,16,24
            uint32_t so = (uint32_t)(r * (PPITCH * 2) + col * 2);
            size_t ga = (size_t)(rowBase + r) * GK + kb + col;
            size_t gb = (size_t)(colBase + r) * GK + kb + col;
            cp_async16(s0 + POFF_AHI + so, Ahi + ga);
            cp_async16(s0 + POFF_ALO + so, Alo + ga);
            cp_async16(s0 + POFF_BHI + so, Bhi + gb);
            cp_async16(s0 + POFF_BLO + so, Blo + gb);
        }
    };

    // ldmatrix lane-address components
    const int lr = lane & 7;
    const int lgA_m = ((lane >> 3) & 1) * 8;   // +8 rows for groups 1,3
    const int lgA_k = (lane >> 4) * 8;         // +8 cols for groups 2,3
    const int lgB_k = ((lane >> 3) & 1) * 8;

    load_chunk(0, 0);
    CP_COMMIT();

    for (int ch = 0; ch < PNCHUNK; ch++) {
        if (ch + 1 < PNCHUNK) {
            load_chunk((ch + 1) & 1, (ch + 1) * PBK);
            CP_COMMIT();
            CP_WAIT(1);
        } else {
            CP_WAIT(0);
        }
        __syncthreads();

        const uint32_t s0 = sb + (ch & 1) * PSTAGE_B;
        const uint32_t aHi = s0 + POFF_AHI, aLo = s0 + POFF_ALO;
        const uint32_t bHi = s0 + POFF_BHI, bLo = s0 + POFF_BLO;

#pragma unroll
        for (int ks = 0; ks < PBK; ks += 16) {
            uint32_t ahi[4][4], alo[4][4];
#pragma unroll
            for (int mt = 0; mt < 4; mt++) {
                int row = wm * 64 + mt * 16 + lgA_m + lr;
                uint32_t off = (uint32_t)(row * (PPITCH * 2) + (ks + lgA_k) * 2);
                ldsm_x4(ahi[mt], aHi + off);
                ldsm_x4(alo[mt], aLo + off);
            }
#pragma unroll
            for (int nt = 0; nt < 4; nt++) {
                int brow = wn * 32 + nt * 8 + lr;
                uint32_t off = (uint32_t)(brow * (PPITCH * 2) + (ks + lgB_k) * 2);
                uint32_t bh[2], bl[2];
                ldsm_x2(bh, bHi + off);
                ldsm_x2(bl, bLo + off);
#pragma unroll
                for (int mt = 0; mt < 4; mt++) {
                    mma16816(acc[mt][nt], ahi[mt], bh);   // hh
                    mma16816(acc[mt][nt], ahi[mt], bl);   // hl
                    mma16816(acc[mt][nt], alo[mt], bh);   // lh
                }
            }
        }
        __syncthreads();
    }

    // Epilogue: c0,c1 -> (row l/4, col 2*(l%4)+{0,1}); c2,c3 -> row+8
#pragma unroll
    for (int mt = 0; mt < 4; mt++) {
#pragma unroll
        for (int nt = 0; nt < 4; nt++) {
            int row = rowBase + wm * 64 + mt * 16 + (lane >> 2);
            int col = colBase + wn * 32 + nt * 8 + (lane & 3) * 2;
            float2 bb = *(const float2*)&bias[col];
            float2 o0 = make_float2(acc[mt][nt][0] + bb.x, acc[mt][nt][1] + bb.y);
            float2 o1 = make_float2(acc[mt][nt][2] + bb.x, acc[mt][nt][3] + bb.y);
            *(float2*)&C[(size_t)row * GN + col] = o0;
            *(float2*)&C[(size_t)(row + 8) * GN + col] = o1;
        }
    }
}

// ---------------------------------------------------------------------------
// Flash-style attention, fp32 (unchanged from the passing R1 kernel).
// ---------------------------------------------------------------------------
#define AQ 128
#define AK 64
#define QP 64
#define KP 65
#define VP 68
#define PP 66
#define ASMEM_FLOATS (AQ * QP + AK * KP + AK * VP + AQ * PP)
#define ASMEM_BYTES (ASMEM_FLOATS * 4 + LK * 4)

__global__ __launch_bounds__(256, 2) void attn_kernel(const int* __restrict__ mask,
                                                      float* __restrict__ out) {
    extern __shared__ __align__(16) float sm[];
    float* Qs = sm;
    float* Ks = Qs + AQ * QP;
    float* Vs = Ks + AK * KP;
    float* Ps = Vs + AK * VP;
    int* Ms = (int*)(Ps + AQ * PP);

    const int tid = threadIdx.x;
    const int tk = tid & 15;
    const int tq = tid >> 4;
    const int qb = blockIdx.x;
    const int h = blockIdx.y;
    const int b = blockIdx.z;
    const int q0 = qb * AQ;

    const float* gq = g_q + (size_t)b * LQ * (NH * DHEAD) + h * DHEAD;
    const float* gk = g_k + (size_t)b * LK * (NH * DHEAD) + h * DHEAD;
    const float* gv = g_v + (size_t)b * LK * (NH * DHEAD) + h * DHEAD;

    for (int i = tid; i < LK; i += 256) Ms[i] = mask[b * LK + i];

#pragma unroll
    for (int i = 0; i < 8; i++) {
        int lin = tid + i * 256;
        int r = lin >> 4, c = (lin & 15) << 2;
        float4 v = *(const float4*)&gq[(size_t)(q0 + r) * (NH * DHEAD) + c];
        *(float4*)&Qs[r * QP + c] = v;
    }
    __syncthreads();

    float m_i[8], l_i[8], O[8][4];
#pragma unroll
    for (int i = 0; i < 8; i++) {
        m_i[i] = -INFINITY;
        l_i[i] = 0.f;
        O[i][0] = O[i][1] = O[i][2] = O[i][3] = 0.f;
    }

    const float* qbase = Qs + (tq * 8) * QP;
    const float* pbase = Ps + (tq * 8) * PP;

    for (int kt = 0; kt < LK; kt += AK) {
#pragma unroll
        for (int i = 0; i < 4; i++) {
            int lin = tid + i * 256;
            int r = lin >> 4, c = (lin & 15) << 2;
            float4 kv = *(const float4*)&gk[(size_t)(kt + r) * (NH * DHEAD) + c];
            Ks[r * KP + c + 0] = kv.x;
            Ks[r * KP + c + 1] = kv.y;
            Ks[r * KP + c + 2] = kv.z;
            Ks[r * KP + c + 3] = kv.w;
            float4 vv = *(const float4*)&gv[(size_t)(kt + r) * (NH * DHEAD) + c];
            *(float4*)&Vs[r * VP + c] = vv;
        }
        __syncthreads();

        float S[8][4];
#pragma unroll
        for (int ii = 0; ii < 8; ii++)
            S[ii][0] = S[ii][1] = S[ii][2] = S[ii][3] = 0.f;

        const float* k0p = Ks + (tk * 4 + 0) * KP;
        const float* k1p = Ks + (tk * 4 + 1) * KP;
        const float* k2p = Ks + (tk * 4 + 2) * KP;
        const float* k3p = Ks + (tk * 4 + 3) * KP;
#pragma unroll 4
        for (int d = 0; d < DHEAD; d++) {
            float a_[8];
#pragma unroll
            for (int ii = 0; ii < 8; ii++) a_[ii] = qbase[ii * QP + d];
            float b0 = k0p[d], b1 = k1p[d], b2 = k2p[d], b3 = k3p[d];
#pragma unroll
            for (int ii = 0; ii < 8; ii++) {
                S[ii][0] += a_[ii] * b0;
                S[ii][1] += a_[ii] * b1;
                S[ii][2] += a_[ii] * b2;
                S[ii][3] += a_[ii] * b3;
            }
        }

        int mk0 = Ms[kt + tk * 4 + 0];
        int mk1 = Ms[kt + tk * 4 + 1];
        int mk2 = Ms[kt + tk * 4 + 2];
        int mk3 = Ms[kt + tk * 4 + 3];
#pragma unroll
        for (int ii = 0; ii < 8; ii++) {
            S[ii][0] = (mk0 == 0) ? -1e9f : S[ii][0] * ATT_SCALE;
            S[ii][1] = (mk1 == 0) ? -1e9f : S[ii][1] * ATT_SCALE;
            S[ii][2] = (mk2 == 0) ? -1e9f : S[ii][2] * ATT_SCALE;
            S[ii][3] = (mk3 == 0) ? -1e9f : S[ii][3] * ATT_SCALE;
        }

#pragma unroll
        for (int ii = 0; ii < 8; ii++) {
            float mx = fmaxf(fmaxf(S[ii][0], S[ii][1]), fmaxf(S[ii][2], S[ii][3]));
            mx = fmaxf(mx, __shfl_xor_sync(0xffffffffu, mx, 1));
            mx = fmaxf(mx, __shfl_xor_sync(0xffffffffu, mx, 2));
            mx = fmaxf(mx, __shfl_xor_sync(0xffffffffu, mx, 4));
            mx = fmaxf(mx, __shfl_xor_sync(0xffffffffu, mx, 8));
            float mnew = fmaxf(m_i[ii], mx);
            float sc = __expf(m_i[ii] - mnew);
            m_i[ii] = mnew;
            float ls = 0.f;
#pragma unroll
            for (int jj = 0; jj < 4; jj++) {
                float p = __expf(S[ii][jj] - mnew);
                S[ii][jj] = p;
                ls += p;
            }
            ls += __shfl_xor_sync(0xffffffffu, ls, 1);
            ls += __shfl_xor_sync(0xffffffffu, ls, 2);
            ls += __shfl_xor_sync(0xffffffffu, ls, 4);
            ls += __shfl_xor_sync(0xffffffffu, ls, 8);
            l_i[ii] = l_i[ii] * sc + ls;
            O[ii][0] *= sc;
            O[ii][1] *= sc;
            O[ii][2] *= sc;
            O[ii][3] *= sc;
        }

#pragma unroll
        for (int ii = 0; ii < 8; ii++) {
#pragma unroll
            for (int jj = 0; jj < 4; jj++)
                Ps[(tq * 8 + ii) * PP + tk * 4 + jj] = S[ii][jj];
        }
        __syncthreads();

#pragma unroll 4
        for (int kj = 0; kj < AK; kj++) {
            float4 v4 = *(const float4*)&Vs[kj * VP + tk * 4];
#pragma unroll
            for (int ii = 0; ii < 8; ii++) {
                float p = pbase[ii * PP + kj];
                O[ii][0] += p * v4.x;
                O[ii][1] += p * v4.y;
                O[ii][2] += p * v4.z;
                O[ii][3] += p * v4.w;
            }
        }
        __syncthreads();
    }

#pragma unroll
    for (int ii = 0; ii < 8; ii++) {
        float inv = 1.f / l_i[ii];
        size_t row = (size_t)b * LQ + q0 + tq * 8 + ii;
        float4 o = make_float4(O[ii][0] * inv, O[ii][1] * inv,
                               O[ii][2] * inv, O[ii][3] * inv);
        *(float4*)&out[row * (NH * DHEAD) + h * DHEAD + tk * 4] = o;
    }
}

// ---------------------------------------------------------------------------
extern "C" void kernel_launch(void* const* d_in, const int* in_sizes, int n_in,
                              void* d_out, int out_size) {
    (void)in_sizes;
    (void)n_in;
    (void)out_size;
    const float* Q = (const float*)d_in[0];
    const float* K = (const float*)d_in[1];
    const float* V = (const float*)d_in[2];
    const int* mask = (const int*)d_in[3];
    const float* Wq = (const float*)d_in[4];
    const float* bq = (const float*)d_in[5];
    const float* Wk = (const float*)d_in[6];
    const float* bk = (const float*)d_in[7];
    const float* Wv = (const float*)d_in[8];
    const float* bv = (const float*)d_in[9];
    float* out = (float*)d_out;

    cudaFuncSetAttribute(proj_mma, cudaFuncAttributeMaxDynamicSharedMemorySize, PSMEM_B);
    cudaFuncSetAttribute(attn_kernel, cudaFuncAttributeMaxDynamicSharedMemorySize,
                         ASMEM_BYTES);

    __nv_bfloat16 *ahi_p, *alo_p, *whi_p, *wlo_p;
    float *gq_p, *gk_p, *gv_p;
    cudaGetSymbolAddress((void**)&ahi_p, g_ahi);
    cudaGetSymbolAddress((void**)&alo_p, g_alo);
    cudaGetSymbolAddress((void**)&whi_p, g_whi);
    cudaGetSymbolAddress((void**)&wlo_p, g_wlo);
    cudaGetSymbolAddress((void**)&gq_p, g_q);
    cudaGetSymbolAddress((void**)&gk_p, g_k);
    cudaGetSymbolAddress((void**)&gv_p, g_v);

    const int n4 = GM * GK / 4;
    dim3 tg(GN / 32, GK / 32);
    dim3 gg(GN / PBN, GM / PBM);   // (8, 64)

    const float* X[3] = {Q, K, V};
    const float* W[3] = {Wq, Wk, Wv};
    const float* Bv[3] = {bq, bk, bv};
    float* Cv[3] = {gq_p, gk_p, gv_p};
    for (int i = 0; i < 3; i++) {
        wtrans_kernel<<<tg, 256>>>(W[i], whi_p, wlo_p);
        split_kernel<<<(n4 + 255) / 256, 256>>>(X[i], (uint2*)ahi_p, (uint2*)alo_p, n4);
        proj_mma<<<gg, 256, PSMEM_B>>>(ahi_p, alo_p, whi_p, wlo_p, Bv[i], Cv[i]);
    }

    dim3 ag(LQ / AQ, NH, BATCH);
    attn_kernel<<<ag, 256, ASMEM_BYTES>>>(mask, out);
}

// round 7
// speedup vs baseline: 2.2732x; 1.7568x over previous
#include <cuda_runtime.h>
#include <cuda_bf16.h>
#include <cstdint>
#include <math.h>

// ---------------------------------------------------------------------------
// Problem constants
// ---------------------------------------------------------------------------
#define BATCH 4
#define NH 16
#define LQ 2048
#define LK 2048
#define DHEAD 64

#define GM 8192            // B*LQ
#define GN 1024            // H*DHEAD
#define GK 1024            // D_MODEL

#define SCALE_L2E 0.1803368801111204f   // (1/8) * log2(e)
#define MASKNEG  -1.442695040e9f        // -1e9 * log2(e)

// Scratch: projected q/k/v as bf16 hi/lo, layout [B, S, H, D]
__device__ __nv_bfloat16 g_qhi[GM * GN / 8 * 8];  // 8192*1024
__device__ __nv_bfloat16 g_qlo[GM * GN / 8 * 8];
__device__ __nv_bfloat16 g_khi[GM * GN / 8 * 8];
__device__ __nv_bfloat16 g_klo[GM * GN / 8 * 8];
__device__ __nv_bfloat16 g_vhi[GM * GN / 8 * 8];
__device__ __nv_bfloat16 g_vlo[GM * GN / 8 * 8];
__device__ __nv_bfloat16 g_ahi[GM * GK];
__device__ __nv_bfloat16 g_alo[GM * GK];
__device__ __nv_bfloat16 g_whi[GN * GK];   // transposed: [n][k]
__device__ __nv_bfloat16 g_wlo[GN * GK];

// ---------------------------------------------------------------------------
// Helpers (baseline PTX: ldmatrix / mma.sync / cp.async)
// ---------------------------------------------------------------------------
__device__ __forceinline__ uint32_t smem_u32(const void* p) {
    uint32_t a;
    asm("{ .reg .u64 t; cvta.to.shared.u64 t, %1; cvt.u32.u64 %0, t; }"
        : "=r"(a) : "l"(p));
    return a;
}
__device__ __forceinline__ void cp_async16(uint32_t s, const void* g) {
    asm volatile("cp.async.cg.shared.global [%0], [%1], 16;" :: "r"(s), "l"(g));
}
#define CP_COMMIT() asm volatile("cp.async.commit_group;")
#define CP_WAIT(n) asm volatile("cp.async.wait_group %0;" :: "n"(n))

__device__ __forceinline__ void ldsm_x4(uint32_t* r, uint32_t addr) {
    asm volatile("ldmatrix.sync.aligned.m8n8.x4.shared.b16 {%0,%1,%2,%3}, [%4];"
                 : "=r"(r[0]), "=r"(r[1]), "=r"(r[2]), "=r"(r[3]) : "r"(addr));
}
__device__ __forceinline__ void ldsm_x2(uint32_t* r, uint32_t addr) {
    asm volatile("ldmatrix.sync.aligned.m8n8.x2.shared.b16 {%0,%1}, [%2];"
                 : "=r"(r[0]), "=r"(r[1]) : "r"(addr));
}
__device__ __forceinline__ void ldsm_x2t(uint32_t* r, uint32_t addr) {
    asm volatile("ldmatrix.sync.aligned.m8n8.x2.trans.shared.b16 {%0,%1}, [%2];"
                 : "=r"(r[0]), "=r"(r[1]) : "r"(addr));
}
__device__ __forceinline__ void mma16816(float* c, const uint32_t* a, const uint32_t* b) {
    asm volatile(
        "mma.sync.aligned.m16n8k16.row.col.f32.bf16.bf16.f32 "
        "{%0,%1,%2,%3}, {%4,%5,%6,%7}, {%8,%9}, {%0,%1,%2,%3};"
        : "+f"(c[0]), "+f"(c[1]), "+f"(c[2]), "+f"(c[3])
        : "r"(a[0]), "r"(a[1]), "r"(a[2]), "r"(a[3]), "r"(b[0]), "r"(b[1]));
}

// (x,y) -> packed bf16x2 hi and lo residual
__device__ __forceinline__ void split2(float x, float y, uint32_t& h, uint32_t& l) {
    __nv_bfloat162 hh = __floats2bfloat162_rn(x, y);
    float hx = __bfloat162float(hh.x), hy = __bfloat162float(hh.y);
    __nv_bfloat162 ll = __floats2bfloat162_rn(x - hx, y - hy);
    h = *(uint32_t*)&hh;
    l = *(uint32_t*)&ll;
}

// ---------------------------------------------------------------------------
// Input conversion kernels
// ---------------------------------------------------------------------------
__device__ __forceinline__ uint32_t pack2(float a, float b) {
    __nv_bfloat162 t = __floats2bfloat162_rn(a, b);
    return *(uint32_t*)&t;
}

__global__ __launch_bounds__(256) void split_kernel(const float* __restrict__ x,
                                                    uint2* __restrict__ hi,
                                                    uint2* __restrict__ lo, int n4) {
    int i = blockIdx.x * 256 + threadIdx.x;
    if (i >= n4) return;
    float4 v = ((const float4*)x)[i];
    float h0 = __bfloat162float(__float2bfloat16(v.x));
    float h1 = __bfloat162float(__float2bfloat16(v.y));
    float h2 = __bfloat162float(__float2bfloat16(v.z));
    float h3 = __bfloat162float(__float2bfloat16(v.w));
    uint2 H, L;
    H.x = pack2(h0, h1);
    H.y = pack2(h2, h3);
    L.x = pack2(v.x - h0, v.y - h1);
    L.y = pack2(v.z - h2, v.w - h3);
    hi[i] = H;
    lo[i] = L;
}

__global__ __launch_bounds__(256) void wtrans_kernel(const float* __restrict__ W,
                                                     __nv_bfloat16* __restrict__ thi,
                                                     __nv_bfloat16* __restrict__ tlo) {
    __shared__ float t[32][33];
    int n0 = blockIdx.x * 32, k0 = blockIdx.y * 32;
    int tx = threadIdx.x & 31, ty0 = threadIdx.x >> 5;
#pragma unroll
    for (int i = 0; i < 4; i++) {
        int ty = ty0 + i * 8;
        t[ty][tx] = W[(size_t)(k0 + ty) * GN + n0 + tx];
    }
    __syncthreads();
#pragma unroll
    for (int i = 0; i < 4; i++) {
        int ty = ty0 + i * 8;
        float v = t[tx][ty];
        __nv_bfloat16 h = __float2bfloat16(v);
        size_t o = (size_t)(n0 + ty) * GK + k0 + tx;
        thi[o] = h;
        tlo[o] = __float2bfloat16(v - __bfloat162float(h));
    }
}

// ---------------------------------------------------------------------------
// Projection GEMM (mma.sync, bf16 hi/lo 3-term). Writes bf16 hi/lo outputs.
// ---------------------------------------------------------------------------
#define PBM 128
#define PBN 128
#define PBK 32
#define PPITCH 40
#define PTILE_B (128 * PPITCH * 2)
#define POFF_AHI 0
#define POFF_ALO (POFF_AHI + PTILE_B)
#define POFF_BHI (POFF_ALO + PTILE_B)
#define POFF_BLO (POFF_BHI + PTILE_B)
#define PSTAGE_B (4 * PTILE_B)
#define PSMEM_B (2 * PSTAGE_B)
#define PNCHUNK (GK / PBK)

__global__ __launch_bounds__(256) void proj_mma(const __nv_bfloat16* __restrict__ Ahi,
                                                const __nv_bfloat16* __restrict__ Alo,
                                                const __nv_bfloat16* __restrict__ Bhi,
                                                const __nv_bfloat16* __restrict__ Blo,
                                                const float* __restrict__ bias,
                                                __nv_bfloat16* __restrict__ Chi,
                                                __nv_bfloat16* __restrict__ Clo) {
    extern __shared__ char smem[];
    const uint32_t sb = smem_u32(smem);
    const int tid = threadIdx.x;
    const int lane = tid & 31;
    const int warp = tid >> 5;
    const int wm = warp & 1;
    const int wn = warp >> 1;
    const int rowBase = blockIdx.y * PBM;
    const int colBase = blockIdx.x * PBN;

    float acc[4][4][4];
#pragma unroll
    for (int i = 0; i < 4; i++)
#pragma unroll
        for (int j = 0; j < 4; j++)
#pragma unroll
            for (int r = 0; r < 4; r++) acc[i][j][r] = 0.f;

    auto load_chunk = [&](int stage, int kb) {
        uint32_t s0 = sb + stage * PSTAGE_B;
#pragma unroll
        for (int i = 0; i < 2; i++) {
            int c = tid + i * 256;
            int r = c >> 2;
            int col = (c & 3) * 8;
            uint32_t so = (uint32_t)(r * (PPITCH * 2) + col * 2);
            size_t ga = (size_t)(rowBase + r) * GK + kb + col;
            size_t gb = (size_t)(colBase + r) * GK + kb + col;
            cp_async16(s0 + POFF_AHI + so, Ahi + ga);
            cp_async16(s0 + POFF_ALO + so, Alo + ga);
            cp_async16(s0 + POFF_BHI + so, Bhi + gb);
            cp_async16(s0 + POFF_BLO + so, Blo + gb);
        }
    };

    const int lr = lane & 7;
    const int lgA_m = ((lane >> 3) & 1) * 8;
    const int lgA_k = (lane >> 4) * 8;
    const int lgB_k = ((lane >> 3) & 1) * 8;

    load_chunk(0, 0);
    CP_COMMIT();

    for (int ch = 0; ch < PNCHUNK; ch++) {
        if (ch + 1 < PNCHUNK) {
            load_chunk((ch + 1) & 1, (ch + 1) * PBK);
            CP_COMMIT();
            CP_WAIT(1);
        } else {
            CP_WAIT(0);
        }
        __syncthreads();

        const uint32_t s0 = sb + (ch & 1) * PSTAGE_B;
        const uint32_t aHi = s0 + POFF_AHI, aLo = s0 + POFF_ALO;
        const uint32_t bHi = s0 + POFF_BHI, bLo = s0 + POFF_BLO;

#pragma unroll
        for (int ks = 0; ks < PBK; ks += 16) {
            uint32_t ahi[4][4], alo[4][4];
#pragma unroll
            for (int mt = 0; mt < 4; mt++) {
                int row = wm * 64 + mt * 16 + lgA_m + lr;
                uint32_t off = (uint32_t)(row * (PPITCH * 2) + (ks + lgA_k) * 2);
                ldsm_x4(ahi[mt], aHi + off);
                ldsm_x4(alo[mt], aLo + off);
            }
#pragma unroll
            for (int nt = 0; nt < 4; nt++) {
                int brow = wn * 32 + nt * 8 + lr;
                uint32_t off = (uint32_t)(brow * (PPITCH * 2) + (ks + lgB_k) * 2);
                uint32_t bh[2], bl[2];
                ldsm_x2(bh, bHi + off);
                ldsm_x2(bl, bLo + off);
#pragma unroll
                for (int mt = 0; mt < 4; mt++) {
                    mma16816(acc[mt][nt], ahi[mt], bh);
                    mma16816(acc[mt][nt], ahi[mt], bl);
                    mma16816(acc[mt][nt], alo[mt], bh);
                }
            }
        }
        __syncthreads();
    }

    // Epilogue: bias add, then split to bf16 hi/lo and store
#pragma unroll
    for (int mt = 0; mt < 4; mt++) {
#pragma unroll
        for (int nt = 0; nt < 4; nt++) {
            int row = rowBase + wm * 64 + mt * 16 + (lane >> 2);
            int col = colBase + wn * 32 + nt * 8 + (lane & 3) * 2;
            float2 bb = *(const float2*)&bias[col];
            float v0 = acc[mt][nt][0] + bb.x, v1 = acc[mt][nt][1] + bb.y;
            float v2 = acc[mt][nt][2] + bb.x, v3 = acc[mt][nt][3] + bb.y;
            uint32_t h, l;
            split2(v0, v1, h, l);
            *(uint32_t*)(Chi + (size_t)row * GN + col) = h;
            *(uint32_t*)(Clo + (size_t)row * GN + col) = l;
            split2(v2, v3, h, l);
            *(uint32_t*)(Chi + (size_t)(row + 8) * GN + col) = h;
            *(uint32_t*)(Clo + (size_t)(row + 8) * GN + col) = l;
        }
    }
}

// ---------------------------------------------------------------------------
// Flash attention on mma.sync tensor cores.
// CTA: 128 queries x (b,h). 8 warps x 16 query rows. KT=64 key tiles,
// cp.async double-buffered k/v (hi/lo). log2-domain online softmax.
// ---------------------------------------------------------------------------
#define AQ 128
#define KT 64
#define APITCH 72                       // bf16 elems per smem row (144 B)
#define AT_QH 0
#define AT_QL (AT_QH + AQ * APITCH * 2)             // 18432
#define AT_MS (AT_QL + AQ * APITCH * 2)             // 36864
#define AT_ST (AT_MS + LK * 4)                      // 45056
#define AT_ARR (KT * APITCH * 2)                    // 9216
#define AT_STG (4 * AT_ARR)                         // 36864
#define AT_SMEM (AT_ST + 2 * AT_STG)                // 118784
#define NKT (LK / KT)                               // 32

__global__ __launch_bounds__(256) void attn_mma(const int* __restrict__ mask,
                                                float* __restrict__ out) {
    extern __shared__ char smem[];
    const uint32_t sb = smem_u32(smem);
    float* Ms = (float*)(smem + AT_MS);

    const int tid = threadIdx.x;
    const int lane = tid & 31;
    const int w = tid >> 5;
    const int q0 = blockIdx.x * AQ;
    const int h = blockIdx.y;
    const int b = blockIdx.z;

    const int lr = lane & 7;
    const int lgA_m = ((lane >> 3) & 1) * 8;
    const int lgA_k = (lane >> 4) * 8;
    const int lgB_k = ((lane >> 3) & 1) * 8;
    const int qr = lane >> 2;           // row within 16-row tile (0..7)
    const int qc = (lane & 3) * 2;      // col pair base

    // ---- prologue loads: q tile + mask + kv tile 0 ----
    const size_t hoff = (size_t)h * DHEAD;
#pragma unroll
    for (int i = 0; i < 8; i++) {
        int seg = tid + i * 256;        // 2048 segs: [0,1024)=qhi, rest qlo
        int arr = seg >> 10;
        int s2 = seg & 1023;
        int row = s2 >> 3, c8 = (s2 & 7) * 8;
        const __nv_bfloat16* g = (arr ? g_qlo : g_qhi) +
            (((size_t)b * LQ + q0 + row) * NH) * DHEAD + hoff + c8;
        cp_async16(sb + (arr ? AT_QL : AT_QH) + (uint32_t)((row * APITCH + c8) * 2), g);
    }
    for (int i = tid; i < LK; i += 256)
        Ms[i] = mask[b * LK + i] ? 1.0f : 0.0f;

    auto load_kv = [&](int stage, int kt) {
        uint32_t s0 = sb + AT_ST + stage * AT_STG;
#pragma unroll
        for (int i = 0; i < 2; i++) {
            int seg = tid + i * 256;    // 512 segs per array
            int row = seg >> 3, c8 = (seg & 7) * 8;
            size_t go = (((size_t)b * LK + kt + row) * NH) * DHEAD + hoff + c8;
            uint32_t so = (uint32_t)((row * APITCH + c8) * 2);
            cp_async16(s0 + 0 * AT_ARR + so, g_khi + go);
            cp_async16(s0 + 1 * AT_ARR + so, g_klo + go);
            cp_async16(s0 + 2 * AT_ARR + so, g_vhi + go);
            cp_async16(s0 + 3 * AT_ARR + so, g_vlo + go);
        }
    };
    load_kv(0, 0);
    CP_COMMIT();
    load_kv(1, KT);
    CP_COMMIT();
    CP_WAIT(1);
    __syncthreads();

    // ---- q fragments to registers ----
    uint32_t qh[4][4], ql[4][4];
#pragma unroll
    for (int ks = 0; ks < 4; ks++) {
        uint32_t off = (uint32_t)(((w * 16 + lgA_m + lr) * APITCH + ks * 16 + lgA_k) * 2);
        ldsm_x4(qh[ks], sb + AT_QH + off);
        ldsm_x4(ql[ks], sb + AT_QL + off);
    }

    float O[8][4];
#pragma unroll
    for (int d = 0; d < 8; d++) O[d][0] = O[d][1] = O[d][2] = O[d][3] = 0.f;
    float m0 = -INFINITY, m1 = -INFINITY, l0 = 0.f, l1 = 0.f;

    for (int it = 0; it < NKT; it++) {
        const uint32_t s0 = sb + AT_ST + (it & 1) * AT_STG;
        const uint32_t kHi = s0, kLo = s0 + AT_ARR;
        const uint32_t vHi = s0 + 2 * AT_ARR, vLo = s0 + 3 * AT_ARR;
        const int ktb = it * KT;

        // ---- S = q . k^T ----
        float S[8][4];
#pragma unroll
        for (int nb = 0; nb < 8; nb++)
            S[nb][0] = S[nb][1] = S[nb][2] = S[nb][3] = 0.f;
#pragma unroll
        for (int ks = 0; ks < 4; ks++) {
#pragma unroll
            for (int nb = 0; nb < 8; nb++) {
                uint32_t off = (uint32_t)(((nb * 8 + lr) * APITCH + ks * 16 + lgB_k) * 2);
                uint32_t kh[2], kl[2];
                ldsm_x2(kh, kHi + off);
                ldsm_x2(kl, kLo + off);
                mma16816(S[nb], qh[ks], kh);
                mma16816(S[nb], qh[ks], kl);
                mma16816(S[nb], ql[ks], kh);
            }
        }

        // ---- scale + mask (log2 domain) ----
#pragma unroll
        for (int nb = 0; nb < 8; nb++) {
            float mf0 = Ms[ktb + nb * 8 + qc];
            float mf1 = Ms[ktb + nb * 8 + qc + 1];
            S[nb][0] = (mf0 != 0.f) ? S[nb][0] * SCALE_L2E : MASKNEG;
            S[nb][1] = (mf1 != 0.f) ? S[nb][1] * SCALE_L2E : MASKNEG;
            S[nb][2] = (mf0 != 0.f) ? S[nb][2] * SCALE_L2E : MASKNEG;
            S[nb][3] = (mf1 != 0.f) ? S[nb][3] * SCALE_L2E : MASKNEG;
        }

        // ---- online softmax ----
        float tm0 = -INFINITY, tm1 = -INFINITY;
#pragma unroll
        for (int nb = 0; nb < 8; nb++) {
            tm0 = fmaxf(tm0, fmaxf(S[nb][0], S[nb][1]));
            tm1 = fmaxf(tm1, fmaxf(S[nb][2], S[nb][3]));
        }
        tm0 = fmaxf(tm0, __shfl_xor_sync(0xffffffffu, tm0, 1));
        tm0 = fmaxf(tm0, __shfl_xor_sync(0xffffffffu, tm0, 2));
        tm1 = fmaxf(tm1, __shfl_xor_sync(0xffffffffu, tm1, 1));
        tm1 = fmaxf(tm1, __shfl_xor_sync(0xffffffffu, tm1, 2));
        float m0n = fmaxf(m0, tm0), m1n = fmaxf(m1, tm1);
        float f0 = exp2f(m0 - m0n), f1 = exp2f(m1 - m1n);
        m0 = m0n;
        m1 = m1n;
#pragma unroll
        for (int d = 0; d < 8; d++) {
            O[d][0] *= f0;
            O[d][1] *= f0;
            O[d][2] *= f1;
            O[d][3] *= f1;
        }
        float rs0 = 0.f, rs1 = 0.f;
#pragma unroll
        for (int nb = 0; nb < 8; nb++) {
            S[nb][0] = exp2f(S[nb][0] - m0);
            S[nb][1] = exp2f(S[nb][1] - m0);
            S[nb][2] = exp2f(S[nb][2] - m1);
            S[nb][3] = exp2f(S[nb][3] - m1);
            rs0 += S[nb][0] + S[nb][1];
            rs1 += S[nb][2] + S[nb][3];
        }
        rs0 += __shfl_xor_sync(0xffffffffu, rs0, 1);
        rs0 += __shfl_xor_sync(0xffffffffu, rs0, 2);
        rs1 += __shfl_xor_sync(0xffffffffu, rs1, 1);
        rs1 += __shfl_xor_sync(0xffffffffu, rs1, 2);
        l0 = l0 * f0 + rs0;
        l1 = l1 * f1 + rs1;

        // ---- pack P hi/lo into A fragments ----
        uint32_t aH[4][4], aL[4][4];
#pragma unroll
        for (int ks2 = 0; ks2 < 4; ks2++) {
            int j0 = 2 * ks2, j1 = 2 * ks2 + 1;
            split2(S[j0][0], S[j0][1], aH[ks2][0], aL[ks2][0]);
            split2(S[j0][2], S[j0][3], aH[ks2][1], aL[ks2][1]);
            split2(S[j1][0], S[j1][1], aH[ks2][2], aL[ks2][2]);
            split2(S[j1][2], S[j1][3], aH[ks2][3], aL[ks2][3]);
        }

        // ---- O += P . V ----
#pragma unroll
        for (int db = 0; db < 8; db++) {
#pragma unroll
            for (int ks2 = 0; ks2 < 4; ks2++) {
                uint32_t off = (uint32_t)(((ks2 * 16 + (lane & 15)) * APITCH + db * 8) * 2);
                uint32_t vh[2], vl[2];
                ldsm_x2t(vh, vHi + off);
                ldsm_x2t(vl, vLo + off);
                mma16816(O[db], aH[ks2], vh);
                mma16816(O[db], aH[ks2], vl);
                mma16816(O[db], aL[ks2], vh);
            }
        }

        __syncthreads();
        if (it + 1 < NKT) {
            if (it + 2 < NKT) {
                load_kv(it & 1, (it + 2) * KT);
                CP_COMMIT();
                CP_WAIT(1);
            } else {
                CP_WAIT(0);
            }
            __syncthreads();
        }
    }

    // ---- normalize and write ----
    float inv0 = 1.f / l0, inv1 = 1.f / l1;
    int row0 = q0 + w * 16 + qr;
#pragma unroll
    for (int db = 0; db < 8; db++) {
        int col = h * DHEAD + db * 8 + qc;
        float2 o0 = make_float2(O[db][0] * inv0, O[db][1] * inv0);
        float2 o1 = make_float2(O[db][2] * inv1, O[db][3] * inv1);
        *(float2*)&out[((size_t)b * LQ + row0) * GN + col] = o0;
        *(float2*)&out[((size_t)b * LQ + row0 + 8) * GN + col] = o1;
    }
}

// ---------------------------------------------------------------------------
extern "C" void kernel_launch(void* const* d_in, const int* in_sizes, int n_in,
                              void* d_out, int out_size) {
    (void)in_sizes;
    (void)n_in;
    (void)out_size;
    const float* Q = (const float*)d_in[0];
    const float* K = (const float*)d_in[1];
    const float* V = (const float*)d_in[2];
    const int* mask = (const int*)d_in[3];
    const float* Wq = (const float*)d_in[4];
    const float* bq = (const float*)d_in[5];
    const float* Wk = (const float*)d_in[6];
    const float* bk = (const float*)d_in[7];
    const float* Wv = (const float*)d_in[8];
    const float* bv = (const float*)d_in[9];
    float* out = (float*)d_out;

    cudaFuncSetAttribute(proj_mma, cudaFuncAttributeMaxDynamicSharedMemorySize, PSMEM_B);
    cudaFuncSetAttribute(attn_mma, cudaFuncAttributeMaxDynamicSharedMemorySize, AT_SMEM);

    __nv_bfloat16 *ahi_p, *alo_p, *whi_p, *wlo_p;
    __nv_bfloat16 *qhi_p, *qlo_p, *khi_p, *klo_p, *vhi_p, *vlo_p;
    cudaGetSymbolAddress((void**)&ahi_p, g_ahi);
    cudaGetSymbolAddress((void**)&alo_p, g_alo);
    cudaGetSymbolAddress((void**)&whi_p, g_whi);
    cudaGetSymbolAddress((void**)&wlo_p, g_wlo);
    cudaGetSymbolAddress((void**)&qhi_p, g_qhi);
    cudaGetSymbolAddress((void**)&qlo_p, g_qlo);
    cudaGetSymbolAddress((void**)&khi_p, g_khi);
    cudaGetSymbolAddress((void**)&klo_p, g_klo);
    cudaGetSymbolAddress((void**)&vhi_p, g_vhi);
    cudaGetSymbolAddress((void**)&vlo_p, g_vlo);

    const int n4 = GM * GK / 4;
    dim3 tg(GN / 32, GK / 32);
    dim3 gg(GN / PBN, GM / PBM);

    const float* X[3] = {Q, K, V};
    const float* W[3] = {Wq, Wk, Wv};
    const float* Bv[3] = {bq, bk, bv};
    __nv_bfloat16* Ch[3] = {qhi_p, khi_p, vhi_p};
    __nv_bfloat16* Cl[3] = {qlo_p, klo_p, vlo_p};
    for (int i = 0; i < 3; i++) {
        wtrans_kernel<<<tg, 256>>>(W[i], whi_p, wlo_p);
        split_kernel<<<(n4 + 255) / 256, 256>>>(X[i], (uint2*)ahi_p, (uint2*)alo_p, n4);
        proj_mma<<<gg, 256, PSMEM_B>>>(ahi_p, alo_p, whi_p, wlo_p, Bv[i], Ch[i], Cl[i]);
    }

    dim3 ag(LQ / AQ, NH, BATCH);
    attn_mma<<<ag, 256, AT_SMEM>>>(mask, out);
}